// round 2
// baseline (speedup 1.0000x reference)
#include <cuda_runtime.h>

// TokenMixer: out = x_pos * (1 - sigmoid(cos_sim_C(x_pre, x_pos)))
// Shapes: [N=4096, B=16, C=512] fp32, row-contiguous along C.
// One warp per (n, b) row. C = 512 floats = 128 float4 = 4 float4 per lane.

static constexpr int C_F4_PER_LANE = 4;   // 512 / 4 / 32

__global__ __launch_bounds__(256, 8)
void tokenmixer_kernel(const float4* __restrict__ pre,
                       const float4* __restrict__ pos,
                       float4* __restrict__ out,
                       int nrows)
{
    const int gwarp = (blockIdx.x * blockDim.x + threadIdx.x) >> 5;
    const int lane  = threadIdx.x & 31;
    if (gwarp >= nrows) return;

    const size_t base = (size_t)gwarp * 128;  // 128 float4 per row
    const float4* a = pre + base;
    const float4* b = pos + base;

    // Front-batch all loads for max MLP (8 LDG.128 in flight per lane).
    float4 av[C_F4_PER_LANE], bv[C_F4_PER_LANE];
#pragma unroll
    for (int i = 0; i < C_F4_PER_LANE; i++) {
        av[i] = a[lane + i * 32];
        bv[i] = b[lane + i * 32];
    }

    float dot = 0.f, na = 0.f, nb = 0.f;
#pragma unroll
    for (int i = 0; i < C_F4_PER_LANE; i++) {
        dot = fmaf(av[i].x, bv[i].x, dot);
        dot = fmaf(av[i].y, bv[i].y, dot);
        dot = fmaf(av[i].z, bv[i].z, dot);
        dot = fmaf(av[i].w, bv[i].w, dot);
        na  = fmaf(av[i].x, av[i].x, na);
        na  = fmaf(av[i].y, av[i].y, na);
        na  = fmaf(av[i].z, av[i].z, na);
        na  = fmaf(av[i].w, av[i].w, na);
        nb  = fmaf(bv[i].x, bv[i].x, nb);
        nb  = fmaf(bv[i].y, bv[i].y, nb);
        nb  = fmaf(bv[i].z, bv[i].z, nb);
        nb  = fmaf(bv[i].w, bv[i].w, nb);
    }

    // Warp tree reduction.
#pragma unroll
    for (int off = 16; off > 0; off >>= 1) {
        dot += __shfl_xor_sync(0xFFFFFFFFu, dot, off);
        na  += __shfl_xor_sync(0xFFFFFFFFu, na,  off);
        nb  += __shfl_xor_sync(0xFFFFFFFFu, nb,  off);
    }

    const float EPS = 1e-12f;
    float denom = fmaxf(sqrtf(na), EPS) * fmaxf(sqrtf(nb), EPS);
    float d = dot / denom;
    // 1 - sigmoid(d) = 1 / (1 + exp(d))
    float w = 1.0f / (1.0f + expf(d));

#pragma unroll
    for (int i = 0; i < C_F4_PER_LANE; i++) {
        float4 o4;
        o4.x = bv[i].x * w;
        o4.y = bv[i].y * w;
        o4.z = bv[i].z * w;
        o4.w = bv[i].w * w;
        out[base + lane + i * 32] = o4;
    }
}

extern "C" void kernel_launch(void* const* d_in, const int* in_sizes, int n_in,
                              void* d_out, int out_size)
{
    const float4* pre = (const float4*)d_in[0];
    const float4* pos = (const float4*)d_in[1];
    float4* out = (float4*)d_out;

    int nrows = in_sizes[0] / 512;           // 65536 rows
    int warps_per_block = 256 / 32;          // 8
    int blocks = (nrows + warps_per_block - 1) / warps_per_block;

    tokenmixer_kernel<<<blocks, 256>>>(pre, pos, out, nrows);
}